// round 1
// baseline (speedup 1.0000x reference)
#include <cuda_runtime.h>

// 4M-step sequential sigmoid recurrence, parallelized via saturation-collapse
// chunking. Each thread owns a chunk of LCHUNK steps and warms up for HWARM
// steps from interval bounds [0,1]; the 10x-gain sigmoid map is strongly
// contracting, so lo/hi collapse to bitwise-equal fp32 within ~50 steps,
// giving the EXACT state at the chunk start. A device flag + always-launched
// single-thread fallback kernel guarantees correctness if collapse ever fails.

#define LCHUNK 256
#define HWARM  256

__device__ int g_fail_flag;

__device__ __forceinline__ float sig10(float t) {
    // sigmoid(10*t) = 1/(1+exp(-10t)); MUFU.EX2 + MUFU.RCP path
    return __fdividef(1.0f, 1.0f + __expf(-10.0f * t));
}

__global__ void __launch_bounds__(128)
scan_chunks(const float* __restrict__ x, const float* __restrict__ W,
            const float* __restrict__ b, const float* __restrict__ net0,
            float* __restrict__ out, int nB)
{
    long c = (long)blockIdx.x * blockDim.x + threadIdx.x;
    long start = c * (long)LCHUNK;
    if (start >= nB) return;

    const float w00 = __ldg(W+0), w01 = __ldg(W+1), w02 = __ldg(W+2);
    const float w10 = __ldg(W+3), w11 = __ldg(W+4), w12 = __ldg(W+5);
    const float w20 = __ldg(W+6), w21 = __ldg(W+7), w22 = __ldg(W+8);
    // fold the -0.5 into b:  t = net + (u - 0.5)
    const float bm0 = __ldg(b+0) - 0.5f;
    const float bm1 = __ldg(b+1) - 0.5f;
    const float bm2 = __ldg(b+2) - 0.5f;

    float n0, n1, n2;

    if (c == 0) {
        n0 = __ldg(net0+0); n1 = __ldg(net0+1); n2 = __ldg(net0+2);
    } else {
        int hw = HWARM;
        if ((long)hw > start) hw = (int)start;
        const float* xp = x + 3 * (start - hw);
        float lo0 = 0.f, lo1 = 0.f, lo2 = 0.f;
        float hi0 = 1.f, hi1 = 1.f, hi2 = 1.f;
        int s = 0;
        bool col = false;
        // Phase A: carry both interval bounds until bitwise collapse.
        for (; s < hw; ++s) {
            float x0 = xp[0], x1 = xp[1], x2 = xp[2]; xp += 3;
            float u0 = fmaf(w00, x0, fmaf(w01, x1, fmaf(w02, x2, bm0)));
            float u1 = fmaf(w10, x0, fmaf(w11, x1, fmaf(w12, x2, bm1)));
            float u2 = fmaf(w20, x0, fmaf(w21, x1, fmaf(w22, x2, bm2)));
            lo0 = sig10(lo0 + u0); lo1 = sig10(lo1 + u1); lo2 = sig10(lo2 + u2);
            hi0 = sig10(hi0 + u0); hi1 = sig10(hi1 + u1); hi2 = sig10(hi2 + u2);
            col = (lo0 == hi0) && (lo1 == hi1) && (lo2 == hi2);
            if (col) { ++s; break; }
        }
        if (!col) atomicOr(&g_fail_flag, 1);
        // Phase B: state is exact; finish remaining warmup single-state.
        for (; s < hw; ++s) {
            float x0 = xp[0], x1 = xp[1], x2 = xp[2]; xp += 3;
            float u0 = fmaf(w00, x0, fmaf(w01, x1, fmaf(w02, x2, bm0)));
            float u1 = fmaf(w10, x0, fmaf(w11, x1, fmaf(w12, x2, bm1)));
            float u2 = fmaf(w20, x0, fmaf(w21, x1, fmaf(w22, x2, bm2)));
            lo0 = sig10(lo0 + u0); lo1 = sig10(lo1 + u1); lo2 = sig10(lo2 + u2);
        }
        n0 = lo0; n1 = lo1; n2 = lo2;
    }

    // Main: produce this chunk's outputs.
    const float* xp = x + 3 * start;
    float* op = out + start;
    int L = LCHUNK;
    if (start + L > (long)nB) L = (int)(nB - start);
    #pragma unroll 4
    for (int j = 0; j < L; ++j) {
        float x0 = xp[0], x1 = xp[1], x2 = xp[2]; xp += 3;
        float u0 = fmaf(w00, x0, fmaf(w01, x1, fmaf(w02, x2, bm0)));
        float u1 = fmaf(w10, x0, fmaf(w11, x1, fmaf(w12, x2, bm1)));
        float u2 = fmaf(w20, x0, fmaf(w21, x1, fmaf(w22, x2, bm2)));
        n0 = sig10(n0 + u0); n1 = sig10(n1 + u1); n2 = sig10(n2 + u2);
        op[j] = fmaf(x0, n0, fmaf(x1, n1, x2 * n2));
    }
}

__global__ void init_flag_kernel() { g_fail_flag = 0; }

// Always launched; early-exits unless some chunk failed to collapse.
__global__ void fallback_kernel(const float* __restrict__ x,
                                const float* __restrict__ W,
                                const float* __restrict__ b,
                                const float* __restrict__ net0,
                                float* __restrict__ out, int nB)
{
    if (g_fail_flag == 0) return;
    if (threadIdx.x != 0 || blockIdx.x != 0) return;
    const float w00 = W[0], w01 = W[1], w02 = W[2];
    const float w10 = W[3], w11 = W[4], w12 = W[5];
    const float w20 = W[6], w21 = W[7], w22 = W[8];
    const float bm0 = b[0] - 0.5f, bm1 = b[1] - 0.5f, bm2 = b[2] - 0.5f;
    float n0 = net0[0], n1 = net0[1], n2 = net0[2];
    const float* xp = x;
    for (int i = 0; i < nB; ++i) {
        float x0 = xp[0], x1 = xp[1], x2 = xp[2]; xp += 3;
        float u0 = fmaf(w00, x0, fmaf(w01, x1, fmaf(w02, x2, bm0)));
        float u1 = fmaf(w10, x0, fmaf(w11, x1, fmaf(w12, x2, bm1)));
        float u2 = fmaf(w20, x0, fmaf(w21, x1, fmaf(w22, x2, bm2)));
        n0 = sig10(n0 + u0); n1 = sig10(n1 + u1); n2 = sig10(n2 + u2);
        out[i] = fmaf(x0, n0, fmaf(x1, n1, x2 * n2));
    }
}

extern "C" void kernel_launch(void* const* d_in, const int* in_sizes, int n_in,
                              void* d_out, int out_size)
{
    // Identify inputs by size (robust to insertion vs. alphabetical order;
    // in both, 'b' precedes 'net0'):
    //   x: 3*B floats, W: 9 floats, b: 3 floats, net0: 3 floats.
    const float *x = 0, *W = 0, *b = 0, *n0p = 0;
    long nB = out_size;
    for (int i = 0; i < n_in; ++i) {
        long sz = in_sizes[i];
        if (sz == 3 * nB)      x = (const float*)d_in[i];
        else if (sz == 9)      W = (const float*)d_in[i];
        else if (sz == 3) {
            if (!b) b = (const float*)d_in[i];
            else    n0p = (const float*)d_in[i];
        }
    }
    float* out = (float*)d_out;

    long nchunk = (nB + LCHUNK - 1) / LCHUNK;
    int threads = 128;
    long blocks = (nchunk + threads - 1) / threads;

    init_flag_kernel<<<1, 1>>>();
    scan_chunks<<<(int)blocks, threads>>>(x, W, b, n0p, out, (int)nB);
    fallback_kernel<<<1, 1>>>(x, W, b, n0p, out, (int)nB);
}

// round 2
// speedup vs baseline: 3.5597x; 3.5597x over previous
#include <cuda_runtime.h>

// Sequential 3-component sigmoid recurrence over B=4M steps, parallelized by
// saturation-collapse chunking (interval bounds collapse bitwise within ~64
// steps). Per-chunk fail flags + fixup kernel + serial fallback guarantee
// correctness regardless of collapse behavior.

#define LCH 128            // steps per chunk (multiple of 8)
#define HW  64             // warmup steps (multiple of 8, < LCH)
#define HW2 512            // fixup warmup
#define TPB 64
#define CL (-14.42695040888963f)   // -10 * log2(e)

__device__ unsigned char g_chunk_fail[65536];
__device__ int g_fail2;

__device__ __forceinline__ float ex2a(float t){ float r; asm("ex2.approx.ftz.f32 %0, %1;" : "=f"(r) : "f"(t)); return r; }
__device__ __forceinline__ float rcpa(float t){ float r; asm("rcp.approx.ftz.f32 %0, %1;" : "=f"(r) : "f"(t)); return r; }
// sigmoid(10*(n+u-0.5)) with v = CL*(u-0.5) precomputed:
__device__ __forceinline__ float sg(float n, float v){
    return rcpa(1.0f + ex2a(fmaf(CL, n, v)));
}

// v_k for one step from raw x (cw = CL*W row, cb = CL*(b-0.5))
#define MAKEV(x0,x1,x2) \
    float v0 = fmaf(cw00,(x0), fmaf(cw01,(x1), fmaf(cw02,(x2), cb0))); \
    float v1 = fmaf(cw10,(x0), fmaf(cw11,(x1), fmaf(cw12,(x2), cb1))); \
    float v2 = fmaf(cw20,(x0), fmaf(cw21,(x1), fmaf(cw22,(x2), cb2)));

#define TWOSTEP(x0,x1,x2) do { \
    MAKEV(x0,x1,x2) \
    lo0=sg(lo0,v0); lo1=sg(lo1,v1); lo2=sg(lo2,v2); \
    hi0=sg(hi0,v0); hi1=sg(hi1,v1); hi2=sg(hi2,v2); } while(0)

#define ONESTEPW(x0,x1,x2) do { \
    MAKEV(x0,x1,x2) \
    lo0=sg(lo0,v0); lo1=sg(lo1,v1); lo2=sg(lo2,v2); } while(0)

#define MAINSTEP(x0,x1,x2,pd) do { \
    MAKEV(x0,x1,x2) \
    n0=sg(n0,v0); n1=sg(n1,v1); n2=sg(n2,v2); \
    pd = fmaf((x0),n0, fmaf((x1),n1, (x2)*n2)); } while(0)

// Expand an 8-step block from six float4s c0..c5 via a per-step macro OP(x0,x1,x2,j)
#define BLOCK8(OP) do { \
    OP(c0.x,c0.y,c0.z,0); OP(c0.w,c1.x,c1.y,1); \
    OP(c1.z,c1.w,c2.x,2); OP(c2.y,c2.z,c2.w,3); \
    OP(c3.x,c3.y,c3.z,4); OP(c3.w,c4.x,c4.y,5); \
    OP(c4.z,c4.w,c5.x,6); OP(c5.y,c5.z,c5.w,7); } while(0)

#define OP_TWO(x0,x1,x2,j)  TWOSTEP(x0,x1,x2)
#define OP_ONE(x0,x1,x2,j)  ONESTEPW(x0,x1,x2)
#define OP_MAIN(x0,x1,x2,j) MAINSTEP(x0,x1,x2,p##j)

#define LOAD6(n0_,n1_,n2_,n3_,n4_,n5_,base) do { \
    n0_=__ldg((base)+0); n1_=__ldg((base)+1); n2_=__ldg((base)+2); \
    n3_=__ldg((base)+3); n4_=__ldg((base)+4); n5_=__ldg((base)+5); } while(0)

__global__ void __launch_bounds__(TPB)
scan_chunks(const float* __restrict__ x, const float* __restrict__ W,
            const float* __restrict__ b, const float* __restrict__ net0,
            float* __restrict__ out, int nchunk, int nB)
{
    int c = blockIdx.x * TPB + threadIdx.x;
    if (c == 0) g_fail2 = 0;
    if (c >= nchunk) return;
    long start = (long)c * LCH;

    const float cb0 = CL*(__ldg(b+0)-0.5f);
    const float cb1 = CL*(__ldg(b+1)-0.5f);
    const float cb2 = CL*(__ldg(b+2)-0.5f);
    const float cw00=CL*__ldg(W+0), cw01=CL*__ldg(W+1), cw02=CL*__ldg(W+2);
    const float cw10=CL*__ldg(W+3), cw11=CL*__ldg(W+4), cw12=CL*__ldg(W+5);
    const float cw20=CL*__ldg(W+6), cw21=CL*__ldg(W+7), cw22=CL*__ldg(W+8);

    float n0, n1, n2;
    unsigned char fail = 0;

    if (c == 0) {
        n0=__ldg(net0+0); n1=__ldg(net0+1); n2=__ldg(net0+2);
    } else {
        // Warmup from start-HW with interval bounds [0,1]; HW*12 bytes is 16B aligned.
        const float4* xv = (const float4*)(x + 3*(start - HW));
        float lo0=0.f, lo1=0.f, lo2=0.f, hi0=1.f, hi1=1.f, hi2=1.f;
        float4 c0,c1,c2,c3,c4,c5, t0,t1,t2,t3,t4,t5;
        LOAD6(c0,c1,c2,c3,c4,c5, xv);
        const int NBK = HW/8;
        int blk = 0;
        bool col = false;
        unsigned mask = __activemask();
        // Phase A: two-state blocks, warp-uniform early exit.
        while (blk < NBK) {
            LOAD6(t0,t1,t2,t3,t4,t5, xv + 6*(blk+1));   // blk+1==NBK reads main chunk: valid
            BLOCK8(OP_TWO);
            c0=t0;c1=t1;c2=t2;c3=t3;c4=t4;c5=t5;
            ++blk;
            col = (lo0==hi0)&&(lo1==hi1)&&(lo2==hi2);
            if (__all_sync(mask, col)) break;
        }
        // Phase B: remaining warmup single-state.
        while (blk < NBK) {
            LOAD6(t0,t1,t2,t3,t4,t5, xv + 6*(blk+1));
            BLOCK8(OP_ONE);
            c0=t0;c1=t1;c2=t2;c3=t3;c4=t4;c5=t5;
            ++blk;
        }
        if (!col) fail = 1;
        n0=lo0; n1=lo1; n2=lo2;
    }
    g_chunk_fail[c] = fail;

    // Main: produce LCH outputs with double-buffered float4 streaming.
    long rem = (long)nB - start;
    if (rem >= LCH) {
        const float4* xv = (const float4*)(x + 3*start);
        float4* ov = (float4*)(out + start);
        float4 c0,c1,c2,c3,c4,c5, t0,t1,t2,t3,t4,t5;
        LOAD6(c0,c1,c2,c3,c4,c5, xv);
        const int MBK = LCH/8;
        #pragma unroll 2
        for (int blk = 0; blk < MBK; ++blk) {
            if (blk+1 < MBK) LOAD6(t0,t1,t2,t3,t4,t5, xv + 6*(blk+1));
            float p0,p1,p2,p3,p4,p5,p6,p7;
            BLOCK8(OP_MAIN);
            ov[2*blk]   = make_float4(p0,p1,p2,p3);
            ov[2*blk+1] = make_float4(p4,p5,p6,p7);
            c0=t0;c1=t1;c2=t2;c3=t3;c4=t4;c5=t5;
        }
    } else {
        const float* xp = x + 3*start;
        for (int j = 0; j < (int)rem; ++j) {
            float x0=xp[0], x1=xp[1], x2=xp[2]; xp += 3;
            float pd; MAINSTEP(x0,x1,x2,pd);
            out[start + j] = pd;
        }
    }
}

// Rare path: chunks whose bounds failed to collapse in HW steps redo with HW2.
__global__ void fixup_kernel(const float* __restrict__ x, const float* __restrict__ W,
                             const float* __restrict__ b, const float* __restrict__ net0,
                             float* __restrict__ out, int nchunk, int nB)
{
    int c = blockIdx.x * blockDim.x + threadIdx.x;
    if (c >= nchunk) return;
    if (!g_chunk_fail[c]) return;
    long start = (long)c * LCH;

    const float cb0 = CL*(b[0]-0.5f), cb1 = CL*(b[1]-0.5f), cb2 = CL*(b[2]-0.5f);
    const float cw00=CL*W[0], cw01=CL*W[1], cw02=CL*W[2];
    const float cw10=CL*W[3], cw11=CL*W[4], cw12=CL*W[5];
    const float cw20=CL*W[6], cw21=CL*W[7], cw22=CL*W[8];

    long hw = start < HW2 ? start : HW2;
    const float* xp = x + 3*(start - hw);
    float lo0=0.f,lo1=0.f,lo2=0.f,hi0=1.f,hi1=1.f,hi2=1.f;
    bool col = false;
    for (long s = 0; s < hw; ++s) {
        float x0=xp[0], x1=xp[1], x2=xp[2]; xp += 3;
        MAKEV(x0,x1,x2)
        lo0=sg(lo0,v0); lo1=sg(lo1,v1); lo2=sg(lo2,v2);
        if (!col) {
            hi0=sg(hi0,v0); hi1=sg(hi1,v1); hi2=sg(hi2,v2);
            col = (lo0==hi0)&&(lo1==hi1)&&(lo2==hi2);
        }
    }
    if (!col && start > 0) atomicOr(&g_fail2, 1);
    float n0=lo0, n1=lo1, n2=lo2;
    if (start == 0) { n0=net0[0]; n1=net0[1]; n2=net0[2]; }
    long L = (start + LCH <= nB) ? LCH : (nB - start);
    for (long j = 0; j < L; ++j) {
        float x0=xp[0], x1=xp[1], x2=xp[2]; xp += 3;
        float pd; MAINSTEP(x0,x1,x2,pd);
        out[start + j] = pd;
    }
}

// Ultimate fallback: full serial scan (only if fixup also failed to collapse).
__global__ void fallback_kernel(const float* __restrict__ x, const float* __restrict__ W,
                                const float* __restrict__ b, const float* __restrict__ net0,
                                float* __restrict__ out, int nB)
{
    if (g_fail2 == 0) return;
    if (threadIdx.x != 0 || blockIdx.x != 0) return;
    const float cb0 = CL*(b[0]-0.5f), cb1 = CL*(b[1]-0.5f), cb2 = CL*(b[2]-0.5f);
    const float cw00=CL*W[0], cw01=CL*W[1], cw02=CL*W[2];
    const float cw10=CL*W[3], cw11=CL*W[4], cw12=CL*W[5];
    const float cw20=CL*W[6], cw21=CL*W[7], cw22=CL*W[8];
    float n0=net0[0], n1=net0[1], n2=net0[2];
    const float* xp = x;
    for (int i = 0; i < nB; ++i) {
        float x0=xp[0], x1=xp[1], x2=xp[2]; xp += 3;
        float pd; MAINSTEP(x0,x1,x2,pd);
        out[i] = pd;
    }
}

extern "C" void kernel_launch(void* const* d_in, const int* in_sizes, int n_in,
                              void* d_out, int out_size)
{
    const float *x = 0, *W = 0, *b = 0, *n0p = 0;
    long nB = out_size;
    for (int i = 0; i < n_in; ++i) {
        long sz = in_sizes[i];
        if (sz == 3 * nB)      x = (const float*)d_in[i];
        else if (sz == 9)      W = (const float*)d_in[i];
        else if (sz == 3) {
            if (!b) b = (const float*)d_in[i];
            else    n0p = (const float*)d_in[i];
        }
    }
    float* out = (float*)d_out;

    int nchunk = (int)((nB + LCH - 1) / LCH);
    int blocks = (nchunk + TPB - 1) / TPB;

    scan_chunks<<<blocks, TPB>>>(x, W, b, n0p, out, nchunk, (int)nB);
    fixup_kernel<<<(nchunk + 127)/128, 128>>>(x, W, b, n0p, out, nchunk, (int)nB);
    fallback_kernel<<<1, 1>>>(x, W, b, n0p, out, (int)nB);
}